// round 10
// baseline (speedup 1.0000x reference)
#include <cuda_runtime.h>
#include <math.h>
#include <float.h>

// Problem constants
#define NB     262144
#define DDIM   256
#define HDIM   256
#define EDIM   5

// Tiling
#define TILE_M   64
#define TILE_K   32
#define NTHREADS 256

// Shared memory layout (floats). Mainloop buffers overlap the epilogue h tile.
#define XS_STRIDE 132                       // 128 duplicated floats + 4 pad per k-row
#define WS_OFF    (TILE_K * XS_STRIDE)      // 4224
#define HS_STRIDE 264
#define HS_FLOATS (TILE_M * HS_STRIDE)      // 16896  (>= 4224 + 32*256 = 12416)
#define W2_OFF    HS_FLOATS
#define B1_OFF    (W2_OFF + HDIM * EDIM)
#define B2_OFF    (B1_OFF + HDIM)
#define SMEM_FLOATS (B2_OFF + 8)
#define SMEM_BYTES  (SMEM_FLOATS * 4)       // 73760 bytes

__device__ __forceinline__ void fma2(unsigned long long& d,
                                     unsigned long long a,
                                     unsigned long long b) {
    // packed 2x fp32 FMA (each half is an exact fp32 fma) — sm_100+ PTX only
    asm("fma.rn.f32x2 %0, %1, %2, %0;" : "+l"(d) : "l"(a), "l"(b));
}

extern __shared__ float smem[];

__global__ void __launch_bounds__(NTHREADS, 2)
router_gating_kernel(const float* __restrict__ x,
                     const float* __restrict__ W1,
                     const float* __restrict__ b1,
                     const float* __restrict__ W2,
                     const float* __restrict__ b2,
                     float* __restrict__ out,
                     int write_idx)
{
    float* xs  = smem;                 // [TILE_K][XS_STRIDE] duplicated-transposed x
    float* ws  = smem + WS_OFF;        // [TILE_K][HDIM]
    float* hs  = smem;                 // [TILE_M][HS_STRIDE] (epilogue, overlaps xs/ws)
    float* w2s = smem + W2_OFF;        // [HDIM*EDIM]
    float* b1s = smem + B1_OFF;        // [HDIM]
    float* b2s = smem + B2_OFF;        // [EDIM]

    const int tid = threadIdx.x;
    const int ty  = tid >> 5;          // 0..7  : row group (8 rows each)
    const int tx  = tid & 31;          // 0..31 : col group (8 cols: tx*4..+3 and 128+tx*4..+3)
    const int row0 = blockIdx.x * TILE_M;

    // Load small tensors
    for (int i = tid; i < HDIM * EDIM; i += NTHREADS) w2s[i] = W2[i];
    if (tid < HDIM) b1s[tid] = b1[tid];
    if (tid < EDIM) b2s[tid] = b2[tid];

    // 8 rows x 4 col-pairs of packed f32x2 accumulators
    // c=0: cols tx*4+{0,1}   c=1: cols tx*4+{2,3}
    // c=2: cols 128+tx*4+{0,1}   c=3: cols 128+tx*4+{2,3}
    unsigned long long acc[8][4];
#pragma unroll
    for (int ri = 0; ri < 8; ri++)
#pragma unroll
        for (int c = 0; c < 4; c++) acc[ri][c] = 0ull;

    // ---------------- mainloop: h_acc = x @ W1 ----------------
    for (int k0 = 0; k0 < DDIM; k0 += TILE_K) {
        __syncthreads();   // previous chunk's reads done before overwrite

        // x tile: 64 rows x 32 cols -> transposed + lane-duplicated into xs
#pragma unroll
        for (int it = 0; it < 2; it++) {
            int v   = tid + NTHREADS * it;       // 0..511
            int row = v >> 3;
            int c4  = (v & 7) << 2;              // k-within-tile base (0,4,...,28)
            float4 xv = *reinterpret_cast<const float4*>(
                &x[(size_t)(row0 + row) * DDIM + k0 + c4]);
            float vv[4] = {xv.x, xv.y, xv.z, xv.w};
#pragma unroll
            for (int u = 0; u < 4; u++) {
                *reinterpret_cast<float2*>(&xs[(c4 + u) * XS_STRIDE + 2 * row]) =
                    make_float2(vv[u], vv[u]);
            }
        }
        // W1 tile: 32 k-rows x 256 cols, direct
#pragma unroll
        for (int it = 0; it < 8; it++) {
            int v  = tid + NTHREADS * it;        // 0..2047
            int r  = v >> 6;
            int c4 = (v & 63) << 2;
            *reinterpret_cast<float4*>(&ws[r * HDIM + c4]) =
                *reinterpret_cast<const float4*>(&W1[(size_t)(k0 + r) * HDIM + c4]);
        }
        __syncthreads();

#pragma unroll 8
        for (int k = 0; k < TILE_K; k++) {
            // a: 8 rows duplicated -> 4x LDS.128, warp-uniform (broadcast, N=1)
            const ulonglong2* ap =
                reinterpret_cast<const ulonglong2*>(&xs[k * XS_STRIDE + ty * 16]);
            ulonglong2 a0 = ap[0], a1 = ap[1], a2 = ap[2], a3 = ap[3];
            unsigned long long av[8] = {a0.x, a0.y, a1.x, a1.y,
                                        a2.x, a2.y, a3.x, a3.y};
            // b: two disjoint LDS.128 at tx*4 and 128+tx*4 (conflict-free phases)
            ulonglong2 b0 = *reinterpret_cast<const ulonglong2*>(
                &ws[k * HDIM + tx * 4]);
            ulonglong2 b1v = *reinterpret_cast<const ulonglong2*>(
                &ws[k * HDIM + 128 + tx * 4]);
            unsigned long long bv[4] = {b0.x, b0.y, b1v.x, b1v.y};
#pragma unroll
            for (int ri = 0; ri < 8; ri++)
#pragma unroll
                for (int c = 0; c < 4; c++)
                    fma2(acc[ri][c], av[ri], bv[c]);
        }
    }

    // ---------------- epilogue: relu + bias -> hs ----------------
    __syncthreads();   // all mainloop smem reads complete before overwrite with h
#pragma unroll
    for (int ri = 0; ri < 8; ri++) {
        int r = ty * 8 + ri;
#pragma unroll
        for (int c = 0; c < 4; c++) {
            float2 v = *reinterpret_cast<float2*>(&acc[ri][c]);
            int cn = (c < 2 ? tx * 4 + c * 2 : 128 + tx * 4 + (c - 2) * 2);
            v.x = fmaxf(v.x + b1s[cn],     0.0f);
            v.y = fmaxf(v.y + b1s[cn + 1], 0.0f);
            *reinterpret_cast<float2*>(&hs[r * HS_STRIDE + cn]) = v;
        }
    }
    __syncthreads();

    // ---------------- logits = h @ W2 + b2 ; top-2 ; softmax ; scatter ----------------
    {
        const int r = tid >> 2;        // 0..63  row within tile
        const int q = tid & 3;         // quarter of H
        float p[EDIM] = {0.f, 0.f, 0.f, 0.f, 0.f};
        const float* hrow = &hs[r * HS_STRIDE + q * 64];
#pragma unroll 4
        for (int j4 = 0; j4 < 16; j4++) {
            float4 h4 = reinterpret_cast<const float4*>(hrow)[j4];
            float hv[4] = {h4.x, h4.y, h4.z, h4.w};
            int jb = q * 64 + j4 * 4;
#pragma unroll
            for (int u = 0; u < 4; u++) {
                const float* wrow = &w2s[(jb + u) * EDIM];
#pragma unroll
                for (int e = 0; e < EDIM; e++) p[e] = fmaf(hv[u], wrow[e], p[e]);
            }
        }
        // reduce the 4 partial sums (lanes 4r..4r+3 are in the same warp)
#pragma unroll
        for (int e = 0; e < EDIM; e++) {
            p[e] += __shfl_xor_sync(0xffffffffu, p[e], 1);
            p[e] += __shfl_xor_sync(0xffffffffu, p[e], 2);
        }

        if (q == 0) {
            float l[EDIM];
#pragma unroll
            for (int e = 0; e < EDIM; e++) l[e] = p[e] + b2s[e];

            // top-2, stable tie-break (lower index wins) == jax.lax.top_k
            float v1 = l[0]; int i1 = 0;
            float v2 = -FLT_MAX; int i2 = 0;
#pragma unroll
            for (int e = 1; e < EDIM; e++) {
                if (l[e] > v1)      { v2 = v1; i2 = i1; v1 = l[e]; i1 = e; }
                else if (l[e] > v2) { v2 = l[e]; i2 = e; }
            }
            // softmax over {v1, v2} with max subtraction (matches jax.nn.softmax)
            float e2 = expf(v2 - v1);
            float s  = 1.0f + e2;
            float g1 = 1.0f / s;
            float g2 = e2 / s;

            size_t row = (size_t)(row0 + r);
            size_t gbase = row * EDIM;
#pragma unroll
            for (int e = 0; e < EDIM; e++) {
                float g = 0.0f;
                if (e == i1) g = g1;
                if (e == i2) g = g2;
                out[gbase + e] = g;
            }
            if (write_idx) {
                size_t ibase = (size_t)NB * EDIM + row * 2;
                out[ibase]     = (float)i1;
                out[ibase + 1] = (float)i2;
            }
        }
    }
}

extern "C" void kernel_launch(void* const* d_in, const int* in_sizes, int n_in,
                              void* d_out, int out_size) {
    const float* x  = (const float*)d_in[0];
    const float* W1 = (const float*)d_in[1];
    const float* b1 = (const float*)d_in[2];
    const float* W2 = (const float*)d_in[3];
    const float* b2 = (const float*)d_in[4];
    float* out = (float*)d_out;

    // Output assumed = flattened (gates[B,5], top_idx[B,2]) in float32.
    // If the harness only compares gates (out_size == B*5), skip index writes.
    int write_idx = (out_size >= NB * (EDIM + 2)) ? 1 : 0;

    cudaFuncSetAttribute(router_gating_kernel,
                         cudaFuncAttributeMaxDynamicSharedMemorySize, SMEM_BYTES);
    router_gating_kernel<<<NB / TILE_M, NTHREADS, SMEM_BYTES>>>(
        x, W1, b1, W2, b2, out, write_idx);
}

// round 12
// speedup vs baseline: 1.1339x; 1.1339x over previous
#include <cuda_runtime.h>
#include <math.h>
#include <float.h>

// Problem constants
#define NB     262144
#define DDIM   256
#define HDIM   256
#define EDIM   5

// Tiling: 64 rows per CTA, 256 threads, thread tile = 16 rows x 4 cols
// (rows packed in pairs inside f32x2 accumulators -> acc[8][4] u64 = 64 regs)
#define TILE_M   64
#define TILE_K   32
#define NTHREADS 256

// Shared memory layout (floats).
// xs: transposed x tile [TILE_K][XT_STRIDE]  (xs[k][row], NOT duplicated)
// ws: W1 tile [TILE_K][HDIM]
// hs: 64-row h tile for epilogue (overlaps xs/ws)
#define XT_STRIDE 66                          // 64 rows + 2 pad (even: LDS.64-aligned)
#define WS_OFF    (TILE_K * XT_STRIDE)        // 2112
#define STAGE_FLOATS (WS_OFF + TILE_K * HDIM) // 10304
#define HS_STRIDE 264
#define HS_FLOATS (TILE_M * HS_STRIDE)        // 16896 (> staging; hs owns [0,16896))
#define W2_OFF    HS_FLOATS
#define B1_OFF    (W2_OFF + HDIM * EDIM)
#define B2_OFF    (B1_OFF + HDIM)
#define SMEM_FLOATS (B2_OFF + 8)
#define SMEM_BYTES  (SMEM_FLOATS * 4)         // 73760 bytes -> 2 CTAs/SM

__device__ __forceinline__ void fma2(unsigned long long& d,
                                     unsigned long long a,
                                     unsigned long long b) {
    // packed 2x fp32 FMA (each half is an exact fp32 fma) — sm_100+ PTX only
    asm("fma.rn.f32x2 %0, %1, %2, %0;" : "+l"(d) : "l"(a), "l"(b));
}

__device__ __forceinline__ unsigned long long dup2(float v) {
    unsigned int u = __float_as_uint(v);
    return ((unsigned long long)u << 32) | (unsigned long long)u;
}

extern __shared__ float smem[];

__global__ void __launch_bounds__(NTHREADS, 2)
router_gating_kernel(const float* __restrict__ x,
                     const float* __restrict__ W1,
                     const float* __restrict__ b1,
                     const float* __restrict__ W2,
                     const float* __restrict__ b2,
                     float* __restrict__ out,
                     int write_idx)
{
    float* xs  = smem;                 // [TILE_K][XT_STRIDE] transposed x
    float* ws  = smem + WS_OFF;        // [TILE_K][HDIM]
    float* hs  = smem;                 // [TILE_M][HS_STRIDE] (epilogue; overlaps staging)
    float* w2s = smem + W2_OFF;        // [HDIM*EDIM]
    float* b1s = smem + B1_OFF;        // [HDIM]
    float* b2s = smem + B2_OFF;        // [EDIM]

    const int tid = threadIdx.x;
    const int ty  = tid >> 6;          // 0..3  : row group (16 rows each); warp-uniform
    const int txc = tid & 63;          // 0..63 : col group (cols txc*4..+3)
    const int row0 = blockIdx.x * TILE_M;

    // Small tensors
    for (int i = tid; i < HDIM * EDIM; i += NTHREADS) w2s[i] = W2[i];
    if (tid < HDIM) b1s[tid] = b1[tid];
    if (tid < EDIM) b2s[tid] = b2[tid];

    // Accumulators: 8 row-pairs x 4 cols of packed f32x2 (64 regs)
    // acc[rp][c]: lo = row ty*16+2rp, hi = row ty*16+2rp+1 ; col = txc*4+c
    unsigned long long acc[8][4];
#pragma unroll
    for (int rp = 0; rp < 8; rp++)
#pragma unroll
        for (int c = 0; c < 4; c++) acc[rp][c] = 0ull;

    // ---------------- mainloop: h_acc = x @ W1 ----------------
    for (int k0 = 0; k0 < DDIM; k0 += TILE_K) {
        __syncthreads();   // previous chunk's reads done before overwrite

        // x tile: 64 rows x 32 k -> transposed xs[k][row] (no duplication)
        // lane kk loads column k0+kk for 8 rows (coalesced 128B per row-iter)
        {
            int kk = tid & 31;
            int rb = (tid >> 5) * 8;           // 8 warps x 8 rows = 64 rows
            const float* xg = &x[(size_t)(row0 + rb) * DDIM + k0 + kk];
            float xv[8];
#pragma unroll
            for (int i = 0; i < 8; i++) xv[i] = xg[(size_t)i * DDIM];
#pragma unroll
            for (int i = 0; i < 8; i++) xs[kk * XT_STRIDE + rb + i] = xv[i];
        }
        // W1 tile: 32 k-rows x 256 cols, direct (conflict-free float4)
#pragma unroll
        for (int it = 0; it < 8; it++) {
            int v  = tid + NTHREADS * it;      // 0..2047
            int r  = v >> 6;
            int c4 = (v & 63) << 2;
            *reinterpret_cast<float4*>(&ws[r * HDIM + c4]) =
                *reinterpret_cast<const float4*>(&W1[(size_t)(k0 + r) * HDIM + c4]);
        }
        __syncthreads();

#pragma unroll 8
        for (int k = 0; k < TILE_K; k++) {
            // a: 8 natural row-pairs via LDS.64, warp-uniform broadcast (N=1)
            const unsigned long long* ap = reinterpret_cast<const unsigned long long*>(
                &xs[k * XT_STRIDE + ty * 16]);
            unsigned long long av[8];
#pragma unroll
            for (int rp = 0; rp < 8; rp++) av[rp] = ap[rp];
            // b: one LDS.128 (conflict-free phases), duplicate in-register (alu pipe)
            float4 q0 = *reinterpret_cast<const float4*>(&ws[k * HDIM + txc * 4]);
            unsigned long long bb[4] = {dup2(q0.x), dup2(q0.y), dup2(q0.z), dup2(q0.w)};
#pragma unroll
            for (int rp = 0; rp < 8; rp++)
#pragma unroll
                for (int c = 0; c < 4; c++)
                    fma2(acc[rp][c], av[rp], bb[c]);
        }
    }

    // ---------------- epilogue: relu + bias -> hs ----------------
    __syncthreads();   // all mainloop smem reads complete before hs overwrite
#pragma unroll
    for (int rp = 0; rp < 8; rp++) {
#pragma unroll
        for (int c = 0; c < 4; c++) {
            float2 v = *reinterpret_cast<float2*>(&acc[rp][c]);
            int col = txc * 4 + c;
            float bb1 = b1s[col];
            hs[(ty * 16 + 2 * rp)     * HS_STRIDE + col] = fmaxf(v.x + bb1, 0.0f);
            hs[(ty * 16 + 2 * rp + 1) * HS_STRIDE + col] = fmaxf(v.y + bb1, 0.0f);
        }
    }
    __syncthreads();

    // ---------------- logits = h @ W2 + b2 ; top-2 ; softmax ; scatter ----------------
    {
        const int r = tid >> 2;        // 0..63  row within tile
        const int q = tid & 3;         // quarter of H
        float p[EDIM] = {0.f, 0.f, 0.f, 0.f, 0.f};
        const float* hrow = &hs[r * HS_STRIDE + q * 64];
#pragma unroll 4
        for (int j4 = 0; j4 < 16; j4++) {
            float4 h4 = reinterpret_cast<const float4*>(hrow)[j4];
            float hv[4] = {h4.x, h4.y, h4.z, h4.w};
            int jb = q * 64 + j4 * 4;
#pragma unroll
            for (int u = 0; u < 4; u++) {
                const float* wr = &w2s[(jb + u) * EDIM];
#pragma unroll
                for (int e = 0; e < EDIM; e++) p[e] = fmaf(hv[u], wr[e], p[e]);
            }
        }
        // reduce the 4 partial sums (lanes 4r..4r+3 are in the same warp)
#pragma unroll
        for (int e = 0; e < EDIM; e++) {
            p[e] += __shfl_xor_sync(0xffffffffu, p[e], 1);
            p[e] += __shfl_xor_sync(0xffffffffu, p[e], 2);
        }

        if (q == 0) {
            float l[EDIM];
#pragma unroll
            for (int e = 0; e < EDIM; e++) l[e] = p[e] + b2s[e];

            // top-2, stable tie-break (lower index wins) == jax.lax.top_k
            float v1 = l[0]; int i1 = 0;
            float v2 = -FLT_MAX; int i2 = 0;
#pragma unroll
            for (int e = 1; e < EDIM; e++) {
                if (l[e] > v1)      { v2 = v1; i2 = i1; v1 = l[e]; i1 = e; }
                else if (l[e] > v2) { v2 = l[e]; i2 = e; }
            }
            // softmax over {v1, v2} with max subtraction (matches jax.nn.softmax)
            float e2 = expf(v2 - v1);
            float s  = 1.0f + e2;
            float g1 = 1.0f / s;
            float g2 = e2 / s;

            size_t row = (size_t)(row0 + r);
            size_t gbase = row * EDIM;
#pragma unroll
            for (int e = 0; e < EDIM; e++) {
                float g = 0.0f;
                if (e == i1) g = g1;
                if (e == i2) g = g2;
                out[gbase + e] = g;
            }
            if (write_idx) {
                size_t ibase = (size_t)NB * EDIM + row * 2;
                out[ibase]     = (float)i1;
                out[ibase + 1] = (float)i2;
            }
        }
    }
}

extern "C" void kernel_launch(void* const* d_in, const int* in_sizes, int n_in,
                              void* d_out, int out_size) {
    const float* x  = (const float*)d_in[0];
    const float* W1 = (const float*)d_in[1];
    const float* b1 = (const float*)d_in[2];
    const float* W2 = (const float*)d_in[3];
    const float* b2 = (const float*)d_in[4];
    float* out = (float*)d_out;

    // Output layout confirmed (R10 pass): gates[B,5] then top_idx[B,2] as float32.
    int write_idx = (out_size >= NB * (EDIM + 2)) ? 1 : 0;

    cudaFuncSetAttribute(router_gating_kernel,
                         cudaFuncAttributeMaxDynamicSharedMemorySize, SMEM_BYTES);
    router_gating_kernel<<<NB / TILE_M, NTHREADS, SMEM_BYTES>>>(
        x, W1, b1, W2, b2, out, write_idx);
}